// round 3
// baseline (speedup 1.0000x reference)
#include <cuda_runtime.h>
#include <math.h>

#define N_NODES   30000
#define N_EDGES   240000
#define DMODEL    256
#define HEADS     4
#define HID       64
#define NUM_LAYERS 3
#define NUM_ET    8
#define NUM_GRAPHS 64
#define NUM_CLASSES 2

// ---------------- scratch (no allocs allowed -> __device__ globals) ----------------
__device__ float g_q[N_NODES * DMODEL];
__device__ float g_k[N_NODES * DMODEL];
__device__ float g_v[N_NODES * DMODEL];
__device__ float g_x[N_NODES * DMODEL];
__device__ int   g_cnt[N_NODES];
__device__ int   g_off[N_NODES + 1];
__device__ int   g_pos[N_NODES];
__device__ int   g_eid[N_EDGES];
__device__ float g_pool[NUM_GRAPHS * DMODEL];
__device__ float g_gcnt[NUM_GRAPHS];

// ---------------- init: zero counters / pool ----------------
__global__ void init_kernel() {
    int t = blockIdx.x * blockDim.x + threadIdx.x;
    int stride = gridDim.x * blockDim.x;
    for (int i = t; i < N_NODES; i += stride) g_cnt[i] = 0;
    for (int i = t; i < NUM_GRAPHS * DMODEL; i += stride) g_pool[i] = 0.0f;
    for (int i = t; i < NUM_GRAPHS; i += stride) g_gcnt[i] = 0.0f;
}

// ---------------- CSR build ----------------
__global__ void hist_kernel(const int* __restrict__ ei) {
    int e = blockIdx.x * blockDim.x + threadIdx.x;
    if (e >= N_EDGES) return;
    int dst = ei[N_EDGES + e];
    atomicAdd(&g_cnt[dst], 1);
}

// single-block exclusive scan over g_cnt -> g_off[0..N], also seed g_pos
__global__ void scan_kernel() {
    __shared__ int s_part[1024];
    const int C = (N_NODES + 1023) / 1024;  // 30
    int t = threadIdx.x;
    int base = t * C;
    int sum = 0;
    for (int i = 0; i < C; i++) {
        int idx = base + i;
        if (idx < N_NODES) sum += g_cnt[idx];
    }
    s_part[t] = sum;
    __syncthreads();
    for (int off = 1; off < 1024; off <<= 1) {
        int v = (t >= off) ? s_part[t - off] : 0;
        __syncthreads();
        s_part[t] += v;
        __syncthreads();
    }
    int run = (t == 0) ? 0 : s_part[t - 1];  // exclusive prefix of chunk
    for (int i = 0; i < C; i++) {
        int idx = base + i;
        if (idx < N_NODES) {
            g_off[idx] = run;
            g_pos[idx] = run;
            run += g_cnt[idx];
        }
    }
    if (t == 1023) g_off[N_NODES] = run;  // == total E
}

__global__ void scatter_kernel(const int* __restrict__ ei) {
    int e = blockIdx.x * blockDim.x + threadIdx.x;
    if (e >= N_EDGES) return;
    int dst = ei[N_EDGES + e];
    int slot = atomicAdd(&g_pos[dst], 1);
    g_eid[slot] = e;
}

// ---------------- copy x into working buffer ----------------
__global__ void copyx_kernel(const float* __restrict__ x) {
    int t = blockIdx.x * blockDim.x + threadIdx.x;
    int stride = gridDim.x * blockDim.x;
    for (int i = t; i < N_NODES * DMODEL; i += stride) g_x[i] = x[i];
}

// ---------------- fp32 tiled GEMM: C = g_x @ W + bias ----------------
// 64x64 block tile, 16x16 threads, 4x4 per thread, BK=16
__global__ void gemm_kernel(const float* __restrict__ W,
                            const float* __restrict__ bias,
                            int which) {
    __shared__ float sA[16][68];  // [k][m], padded
    __shared__ float sB[16][64];  // [k][n]
    const float* __restrict__ A = g_x;
    float* __restrict__ C = (which == 0) ? g_q : ((which == 1) ? g_k : g_v);

    int tid = threadIdx.x;
    int tx = tid & 15, ty = tid >> 4;
    int m0 = blockIdx.y * 64, n0 = blockIdx.x * 64;

    float acc[4][4];
#pragma unroll
    for (int i = 0; i < 4; i++)
#pragma unroll
        for (int j = 0; j < 4; j++) acc[i][j] = 0.0f;

    int lm = tid >> 2;            // 0..63  A row
    int lk = (tid & 3) * 4;       // 0,4,8,12
    int bkr = tid >> 4;           // 0..15  B row
    int bn = (tid & 15) * 4;      // 0..60

    for (int k0 = 0; k0 < DMODEL; k0 += 16) {
        float4 a4;
        if (m0 + lm < N_NODES)
            a4 = *(const float4*)(A + (size_t)(m0 + lm) * DMODEL + k0 + lk);
        else
            a4 = make_float4(0.f, 0.f, 0.f, 0.f);
        sA[lk + 0][lm] = a4.x;
        sA[lk + 1][lm] = a4.y;
        sA[lk + 2][lm] = a4.z;
        sA[lk + 3][lm] = a4.w;

        float4 b4 = *(const float4*)(W + (size_t)(k0 + bkr) * DMODEL + n0 + bn);
        *(float4*)(&sB[bkr][bn]) = b4;
        __syncthreads();

#pragma unroll
        for (int k = 0; k < 16; k++) {
            float a[4], b[4];
#pragma unroll
            for (int i = 0; i < 4; i++) a[i] = sA[k][ty * 4 + i];
#pragma unroll
            for (int j = 0; j < 4; j++) b[j] = sB[k][tx * 4 + j];
#pragma unroll
            for (int i = 0; i < 4; i++)
#pragma unroll
                for (int j = 0; j < 4; j++) acc[i][j] += a[i] * b[j];
        }
        __syncthreads();
    }

#pragma unroll
    for (int i = 0; i < 4; i++) {
        int m = m0 + ty * 4 + i;
        if (m >= N_NODES) continue;
#pragma unroll
        for (int j = 0; j < 4; j++) {
            int n = n0 + tx * 4 + j;
            C[(size_t)m * DMODEL + n] = acc[i][j] + bias[n];
        }
    }
}

// ---------------- attention gather: one warp per dst node, online softmax ----------------
__global__ void attn_kernel(const int* __restrict__ ei,
                            const int* __restrict__ etype,
                            const float* __restrict__ Eemb_l) {
    __shared__ float s_ete[NUM_ET * DMODEL];
    for (int i = threadIdx.x; i < NUM_ET * DMODEL; i += blockDim.x)
        s_ete[i] = Eemb_l[i];
    __syncthreads();

    int gw = (blockIdx.x * blockDim.x + threadIdx.x) >> 5;
    int lane = threadIdx.x & 31;
    if (gw >= N_NODES) return;
    int node = gw;

    float qr[8];
#pragma unroll
    for (int r = 0; r < 8; r++) qr[r] = g_q[(size_t)node * DMODEL + r * 32 + lane];

    int beg = g_off[node], end = g_off[node + 1];
    float m[4] = {-INFINITY, -INFINITY, -INFINITY, -INFINITY};
    float den[4] = {0.f, 0.f, 0.f, 0.f};
    float acc[8] = {0.f, 0.f, 0.f, 0.f, 0.f, 0.f, 0.f, 0.f};
    const float scale = 0.125f;  // 1/sqrt(64)

    for (int t = beg; t < end; t++) {
        int e = g_eid[t];
        int src = ei[e];
        int et = etype[e];
        const float* kb = g_k + (size_t)src * DMODEL;
        const float* vb = g_v + (size_t)src * DMODEL;
        const float* eb = s_ete + et * DMODEL;

        float ph[4] = {0.f, 0.f, 0.f, 0.f};
        float vv[8];
#pragma unroll
        for (int r = 0; r < 8; r++) {
            int d = r * 32 + lane;
            float ev = eb[d];
            float kk = kb[d] + ev;
            ph[r >> 1] += qr[r] * kk;
            vv[r] = vb[d] + ev;
        }

        float p[4], sc[4];
#pragma unroll
        for (int h = 0; h < 4; h++) {
            float s = ph[h];
#pragma unroll
            for (int o = 16; o > 0; o >>= 1) s += __shfl_xor_sync(0xffffffffu, s, o);
            s *= scale;
            float nm = fmaxf(m[h], s);
            sc[h] = __expf(m[h] - nm);
            p[h] = __expf(s - nm);
            den[h] = den[h] * sc[h] + p[h];
            m[h] = nm;
        }
#pragma unroll
        for (int r = 0; r < 8; r++) {
            int h = r >> 1;
            acc[r] = acc[r] * sc[h] + p[h] * vv[r];
        }
    }

#pragma unroll
    for (int r = 0; r < 8; r++) {
        float o = acc[r] / (den[r >> 1] + 1e-16f);
        g_x[(size_t)node * DMODEL + r * 32 + lane] = (o > 0.f) ? o : expm1f(o);
    }
}

// ---------------- global mean pool (atomics into tiny per-graph buffers) ----------------
__global__ void pool_kernel(const int* __restrict__ batch) {
    int t = blockIdx.x * blockDim.x + threadIdx.x;
    const int SEGS = DMODEL / 4;  // 64
    int total = N_NODES * SEGS;
    if (t >= total) return;
    int node = t / SEGS;
    int seg = t % SEGS;
    int b = batch[node];
    float4 v = *(const float4*)(g_x + (size_t)node * DMODEL + seg * 4);
    atomicAdd(&g_pool[b * DMODEL + seg * 4 + 0], v.x);
    atomicAdd(&g_pool[b * DMODEL + seg * 4 + 1], v.y);
    atomicAdd(&g_pool[b * DMODEL + seg * 4 + 2], v.z);
    atomicAdd(&g_pool[b * DMODEL + seg * 4 + 3], v.w);
    if (seg == 0) atomicAdd(&g_gcnt[b], 1.0f);
}

// ---------------- GRU (h0 = 0, one step) + FC ----------------
__global__ void gru_kernel(const float* __restrict__ W_ih,
                           const float* __restrict__ b_ih,
                           const float* __restrict__ b_hh,
                           const float* __restrict__ W_fc,
                           const float* __restrict__ b_fc,
                           float* __restrict__ out) {
    __shared__ float gv[DMODEL];
    __shared__ float gi[3 * HID];
    __shared__ float hh[HID];
    int g = blockIdx.x, t = threadIdx.x;
    float cnt = fmaxf(g_gcnt[g], 1.0f);
    if (t < DMODEL) gv[t] = g_pool[g * DMODEL + t] / cnt;
    __syncthreads();
    if (t < 3 * HID) {
        float s = b_ih[t];
        const float* w = W_ih + (size_t)t * DMODEL;
        for (int k = 0; k < DMODEL; k++) s += gv[k] * w[k];
        gi[t] = s;
    }
    __syncthreads();
    if (t < HID) {
        // gh = h0 @ W_hh^T + b_hh = b_hh  (h0 == 0)
        float r = 1.0f / (1.0f + __expf(-(gi[t] + b_hh[t])));
        float z = 1.0f / (1.0f + __expf(-(gi[HID + t] + b_hh[HID + t])));
        float n = tanhf(gi[2 * HID + t] + r * b_hh[2 * HID + t]);
        hh[t] = (1.0f - z) * n;  // + z*h0 == 0
    }
    __syncthreads();
    if (t < NUM_CLASSES) {
        float s = b_fc[t];
        const float* w = W_fc + (size_t)t * HID;
        for (int k = 0; k < HID; k++) s += hh[k] * w[k];
        out[g * NUM_CLASSES + t] = s;
    }
}

// ---------------- launch ----------------
extern "C" void kernel_launch(void* const* d_in, const int* in_sizes, int n_in,
                              void* d_out, int out_size) {
    const float* x     = (const float*)d_in[0];
    const int*   ei    = (const int*)d_in[1];
    const int*   batch = (const int*)d_in[2];
    const int*   etype = (const int*)d_in[3];
    const float* Wq    = (const float*)d_in[4];
    const float* bq    = (const float*)d_in[5];
    const float* Wk    = (const float*)d_in[6];
    const float* bk    = (const float*)d_in[7];
    const float* Wv    = (const float*)d_in[8];
    const float* bv    = (const float*)d_in[9];
    const float* Eemb  = (const float*)d_in[10];
    const float* W_ih  = (const float*)d_in[11];
    const float* b_ih  = (const float*)d_in[12];
    // d_in[13] = W_hh (unused: h0 == 0)
    const float* b_hh  = (const float*)d_in[14];
    const float* W_fc  = (const float*)d_in[15];
    const float* b_fc  = (const float*)d_in[16];
    float* out = (float*)d_out;

    init_kernel<<<64, 256>>>();
    hist_kernel<<<(N_EDGES + 255) / 256, 256>>>(ei);
    scan_kernel<<<1, 1024>>>();
    scatter_kernel<<<(N_EDGES + 255) / 256, 256>>>(ei);
    copyx_kernel<<<1024, 256>>>(x);

    dim3 ggrid(DMODEL / 64, (N_NODES + 63) / 64);
    int ablocks = (N_NODES * 32 + 255) / 256;  // one warp per node, 8 warps/block

    for (int l = 0; l < NUM_LAYERS; l++) {
        const float* wq = Wq + (size_t)l * DMODEL * DMODEL;
        const float* wk = Wk + (size_t)l * DMODEL * DMODEL;
        const float* wv = Wv + (size_t)l * DMODEL * DMODEL;
        gemm_kernel<<<ggrid, 256>>>(wq, bq + l * DMODEL, 0);
        gemm_kernel<<<ggrid, 256>>>(wk, bk + l * DMODEL, 1);
        gemm_kernel<<<ggrid, 256>>>(wv, bv + l * DMODEL, 2);
        attn_kernel<<<ablocks, 256>>>(ei, etype, Eemb + (size_t)l * NUM_ET * DMODEL);
    }

    pool_kernel<<<(N_NODES * (DMODEL / 4) + 255) / 256, 256>>>(batch);
    gru_kernel<<<NUM_GRAPHS, 256>>>(W_ih, b_ih, b_hh, W_fc, b_fc, out);
}

// round 9
// speedup vs baseline: 1.7235x; 1.7235x over previous
#include <cuda_runtime.h>
#include <math.h>
#include <stdint.h>

#define N_NODES   30000
#define N_EDGES   240000
#define DMODEL    256
#define HEADS     4
#define HID       64
#define NUM_LAYERS 3
#define NUM_ET    8
#define NUM_GRAPHS 64
#define NUM_CLASSES 2

// ---------------- scratch (no allocs allowed -> __device__ globals) ----------------
__device__ float g_q[N_NODES * DMODEL];
__device__ float g_k[N_NODES * DMODEL];
__device__ float g_v[N_NODES * DMODEL];
__device__ float g_x[N_NODES * DMODEL];
__device__ float g_wt[9 * DMODEL * DMODEL];   // transposed weights: [l*3+w][n][k]
__device__ int   g_cnt[N_NODES];
__device__ int   g_off[N_NODES + 1];
__device__ int   g_pos[N_NODES];
__device__ int   g_eid[N_EDGES];
__device__ float g_pool[NUM_GRAPHS * DMODEL];
__device__ float g_gcnt[NUM_GRAPHS];

__device__ __forceinline__ uint32_t totf32(float f) {
    uint32_t u;
    asm("cvt.rna.tf32.f32 %0, %1;" : "=r"(u) : "f"(f));
    return u;
}

// ---------------- init ----------------
__global__ void init_kernel() {
    int t = blockIdx.x * blockDim.x + threadIdx.x;
    int stride = gridDim.x * blockDim.x;
    for (int i = t; i < N_NODES; i += stride) g_cnt[i] = 0;
    for (int i = t; i < NUM_GRAPHS * DMODEL; i += stride) g_pool[i] = 0.0f;
    for (int i = t; i < NUM_GRAPHS; i += stride) g_gcnt[i] = 0.0f;
}

// ---------------- CSR build ----------------
__global__ void hist_kernel(const int* __restrict__ ei) {
    int e = blockIdx.x * blockDim.x + threadIdx.x;
    if (e >= N_EDGES) return;
    atomicAdd(&g_cnt[ei[N_EDGES + e]], 1);
}

__global__ void scan_kernel() {
    __shared__ int s_part[1024];
    const int C = (N_NODES + 1023) / 1024;
    int t = threadIdx.x;
    int base = t * C;
    int sum = 0;
    for (int i = 0; i < C; i++) { int idx = base + i; if (idx < N_NODES) sum += g_cnt[idx]; }
    s_part[t] = sum;
    __syncthreads();
    for (int off = 1; off < 1024; off <<= 1) {
        int v = (t >= off) ? s_part[t - off] : 0;
        __syncthreads();
        s_part[t] += v;
        __syncthreads();
    }
    int run = (t == 0) ? 0 : s_part[t - 1];
    for (int i = 0; i < C; i++) {
        int idx = base + i;
        if (idx < N_NODES) { g_off[idx] = run; g_pos[idx] = run; run += g_cnt[idx]; }
    }
    if (t == 1023) g_off[N_NODES] = run;
}

__global__ void scatter_kernel(const int* __restrict__ ei) {
    int e = blockIdx.x * blockDim.x + threadIdx.x;
    if (e >= N_EDGES) return;
    int slot = atomicAdd(&g_pos[ei[N_EDGES + e]], 1);
    g_eid[slot] = e;
}

__global__ void copyx_kernel(const float* __restrict__ x) {
    int t = blockIdx.x * blockDim.x + threadIdx.x;
    int stride = gridDim.x * blockDim.x;
    for (int i = t; i < N_NODES * DMODEL; i += stride) g_x[i] = x[i];
}

// ---------------- weight transpose: g_wt[idx][n][k] = W[idx][k][n] ----------------
__global__ void transpose_w(const float* __restrict__ Wq, const float* __restrict__ Wk,
                            const float* __restrict__ Wv) {
    int t = blockIdx.x * blockDim.x + threadIdx.x;
    int total = 9 * DMODEL * DMODEL;
    if (t >= total) return;
    int idx = t >> 16;
    int rem = t & 65535;
    int n = rem >> 8;
    int k = rem & 255;
    int l = idx / 3, w = idx % 3;
    const float* W = (w == 0) ? Wq : ((w == 1) ? Wk : Wv);
    g_wt[t] = W[(size_t)l * DMODEL * DMODEL + (size_t)k * DMODEL + n];
}

// ---------------- tf32 mma.sync fused QKV GEMM ----------------
// CTA: 128(M) x 128(N) per pass (2 passes for N=256), 8 warps 4(m) x 2(n),
// warp tile 32x64. A resident in SMEM (stride 260 -> conflict-free frags),
// B streamed in K=64 chunks (stride 68).
#define A_STRIDE 260
#define B_STRIDE 68
#define SMEM_G ((128 * A_STRIDE + 128 * B_STRIDE) * 4)

__device__ __forceinline__ void mma_tf32(float* c, uint32_t a0, uint32_t a1,
                                         uint32_t a2, uint32_t a3,
                                         uint32_t b0, uint32_t b1) {
    asm volatile(
        "mma.sync.aligned.m16n8k8.row.col.f32.tf32.tf32.f32 "
        "{%0,%1,%2,%3}, {%4,%5,%6,%7}, {%8,%9}, {%0,%1,%2,%3};"
        : "+f"(c[0]), "+f"(c[1]), "+f"(c[2]), "+f"(c[3])
        : "r"(a0), "r"(a1), "r"(a2), "r"(a3), "r"(b0), "r"(b1));
}

__global__ void __launch_bounds__(256, 1)
gemm_qkv_kernel(const float* __restrict__ bq, const float* __restrict__ bk,
                const float* __restrict__ bv, int l) {
    extern __shared__ float smem[];
    float* sA = smem;                       // [128][A_STRIDE]
    float* sB = smem + 128 * A_STRIDE;      // [128][B_STRIDE]

    int tid = threadIdx.x;
    int wid = tid >> 5, lane = tid & 31;
    int g = lane >> 2, tig = lane & 3;
    int wm = (wid & 3) * 32;                // warp m-base within tile
    int wn = (wid >> 2) * 64;               // warp n-base within pass
    int m0 = blockIdx.x * 128;

    // ---- load A tile [128 x 256] fp32 -> tf32 into padded SMEM
    for (int i = tid; i < 128 * 64; i += 256) {
        int r = i >> 6;
        int c4 = (i & 63) * 4;
        float4 v = make_float4(0.f, 0.f, 0.f, 0.f);
        if (m0 + r < N_NODES) v = *(const float4*)(g_x + (size_t)(m0 + r) * DMODEL + c4);
        float4 u;
        u.x = __uint_as_float(totf32(v.x));
        u.y = __uint_as_float(totf32(v.y));
        u.z = __uint_as_float(totf32(v.z));
        u.w = __uint_as_float(totf32(v.w));
        *(float4*)(sA + r * A_STRIDE + c4) = u;
    }

    for (int w = 0; w < 3; w++) {
        const float* __restrict__ wt = g_wt + (size_t)(l * 3 + w) * DMODEL * DMODEL;
        float* __restrict__ dstp = (w == 0) ? g_q : ((w == 1) ? g_k : g_v);
        const float* __restrict__ bias = (w == 0) ? bq : ((w == 1) ? bk : bv);

        for (int nb = 0; nb < 2; nb++) {
            int n0 = nb * 128;
            float acc[2][8][4];
#pragma unroll
            for (int mi = 0; mi < 2; mi++)
#pragma unroll
                for (int ni = 0; ni < 8; ni++)
#pragma unroll
                    for (int j = 0; j < 4; j++) acc[mi][ni][j] = 0.f;

            for (int kc = 0; kc < 4; kc++) {
                __syncthreads();   // protect sB from previous chunk's readers
                // load B chunk: rows n0..n0+127, k kc*64..+63
                for (int i = tid; i < 128 * 16; i += 256) {
                    int nr = i >> 4;
                    int c4 = (i & 15) * 4;
                    float4 v = *(const float4*)(wt + (size_t)(n0 + nr) * DMODEL + kc * 64 + c4);
                    float4 u;
                    u.x = __uint_as_float(totf32(v.x));
                    u.y = __uint_as_float(totf32(v.y));
                    u.z = __uint_as_float(totf32(v.z));
                    u.w = __uint_as_float(totf32(v.w));
                    *(float4*)(sB + nr * B_STRIDE + c4) = u;
                }
                __syncthreads();

#pragma unroll
                for (int ks = 0; ks < 8; ks++) {
                    int kl = ks * 8;              // local k within chunk (for sB)
                    int kg = kc * 64 + kl;        // global k (for sA)  <-- BUGFIX
                    uint32_t a[2][4];
#pragma unroll
                    for (int mi = 0; mi < 2; mi++) {
                        int r0 = wm + mi * 16 + g;
                        a[mi][0] = __float_as_uint(sA[r0 * A_STRIDE + kg + tig]);
                        a[mi][1] = __float_as_uint(sA[(r0 + 8) * A_STRIDE + kg + tig]);
                        a[mi][2] = __float_as_uint(sA[r0 * A_STRIDE + kg + tig + 4]);
                        a[mi][3] = __float_as_uint(sA[(r0 + 8) * A_STRIDE + kg + tig + 4]);
                    }
                    uint32_t b[8][2];
#pragma unroll
                    for (int ni = 0; ni < 8; ni++) {
                        int nr = wn + ni * 8 + g;
                        b[ni][0] = __float_as_uint(sB[nr * B_STRIDE + kl + tig]);
                        b[ni][1] = __float_as_uint(sB[nr * B_STRIDE + kl + tig + 4]);
                    }
#pragma unroll
                    for (int mi = 0; mi < 2; mi++)
#pragma unroll
                        for (int ni = 0; ni < 8; ni++)
                            mma_tf32(acc[mi][ni], a[mi][0], a[mi][1], a[mi][2], a[mi][3],
                                     b[ni][0], b[ni][1]);
                }
            }

            // ---- epilogue: bias + store
#pragma unroll
            for (int mi = 0; mi < 2; mi++) {
                int r0 = m0 + wm + mi * 16 + g;
                int r1 = r0 + 8;
#pragma unroll
                for (int ni = 0; ni < 8; ni++) {
                    int col = n0 + wn + ni * 8 + tig * 2;
                    float b0 = bias[col], b1 = bias[col + 1];
                    if (r0 < N_NODES) {
                        float2 o0 = make_float2(acc[mi][ni][0] + b0, acc[mi][ni][1] + b1);
                        *(float2*)(dstp + (size_t)r0 * DMODEL + col) = o0;
                    }
                    if (r1 < N_NODES) {
                        float2 o1 = make_float2(acc[mi][ni][2] + b0, acc[mi][ni][3] + b1);
                        *(float2*)(dstp + (size_t)r1 * DMODEL + col) = o1;
                    }
                }
            }
        }
    }
}

// ---------------- attention gather: one warp per dst node, online softmax ----------------
__global__ void attn_kernel(const int* __restrict__ ei,
                            const int* __restrict__ etype,
                            const float* __restrict__ Eemb_l) {
    __shared__ float s_ete[NUM_ET * DMODEL];
    for (int i = threadIdx.x; i < NUM_ET * DMODEL; i += blockDim.x)
        s_ete[i] = Eemb_l[i];
    __syncthreads();

    int gw = (blockIdx.x * blockDim.x + threadIdx.x) >> 5;
    int lane = threadIdx.x & 31;
    if (gw >= N_NODES) return;
    int node = gw;

    float qr[8];
#pragma unroll
    for (int r = 0; r < 8; r++) qr[r] = g_q[(size_t)node * DMODEL + r * 32 + lane];

    int beg = g_off[node], end = g_off[node + 1];
    float m[4] = {-INFINITY, -INFINITY, -INFINITY, -INFINITY};
    float den[4] = {0.f, 0.f, 0.f, 0.f};
    float acc[8] = {0.f, 0.f, 0.f, 0.f, 0.f, 0.f, 0.f, 0.f};
    const float scale = 0.125f;

    for (int t = beg; t < end; t++) {
        int e = g_eid[t];
        int src = ei[e];
        int et = etype[e];
        const float* kb = g_k + (size_t)src * DMODEL;
        const float* vb = g_v + (size_t)src * DMODEL;
        const float* eb = s_ete + et * DMODEL;

        float ph[4] = {0.f, 0.f, 0.f, 0.f};
        float vv[8];
#pragma unroll
        for (int r = 0; r < 8; r++) {
            int d = r * 32 + lane;
            float ev = eb[d];
            float kk = kb[d] + ev;
            ph[r >> 1] += qr[r] * kk;
            vv[r] = vb[d] + ev;
        }

        float p[4], sc[4];
#pragma unroll
        for (int h = 0; h < 4; h++) {
            float s = ph[h];
#pragma unroll
            for (int o = 16; o > 0; o >>= 1) s += __shfl_xor_sync(0xffffffffu, s, o);
            s *= scale;
            float nm = fmaxf(m[h], s);
            sc[h] = __expf(m[h] - nm);
            p[h] = __expf(s - nm);
            den[h] = den[h] * sc[h] + p[h];
            m[h] = nm;
        }
#pragma unroll
        for (int r = 0; r < 8; r++) {
            int h = r >> 1;
            acc[r] = acc[r] * sc[h] + p[h] * vv[r];
        }
    }

#pragma unroll
    for (int r = 0; r < 8; r++) {
        float o = acc[r] / (den[r >> 1] + 1e-16f);
        g_x[(size_t)node * DMODEL + r * 32 + lane] = (o > 0.f) ? o : expm1f(o);
    }
}

// ---------------- global mean pool ----------------
__global__ void pool_kernel(const int* __restrict__ batch) {
    int t = blockIdx.x * blockDim.x + threadIdx.x;
    const int SEGS = DMODEL / 4;
    int total = N_NODES * SEGS;
    if (t >= total) return;
    int node = t / SEGS;
    int seg = t % SEGS;
    int b = batch[node];
    float4 v = *(const float4*)(g_x + (size_t)node * DMODEL + seg * 4);
    atomicAdd(&g_pool[b * DMODEL + seg * 4 + 0], v.x);
    atomicAdd(&g_pool[b * DMODEL + seg * 4 + 1], v.y);
    atomicAdd(&g_pool[b * DMODEL + seg * 4 + 2], v.z);
    atomicAdd(&g_pool[b * DMODEL + seg * 4 + 3], v.w);
    if (seg == 0) atomicAdd(&g_gcnt[b], 1.0f);
}

// ---------------- GRU + FC ----------------
__global__ void gru_kernel(const float* __restrict__ W_ih,
                           const float* __restrict__ b_ih,
                           const float* __restrict__ b_hh,
                           const float* __restrict__ W_fc,
                           const float* __restrict__ b_fc,
                           float* __restrict__ out) {
    __shared__ float gv[DMODEL];
    __shared__ float gi[3 * HID];
    __shared__ float hh[HID];
    int g = blockIdx.x, t = threadIdx.x;
    float cnt = fmaxf(g_gcnt[g], 1.0f);
    if (t < DMODEL) gv[t] = g_pool[g * DMODEL + t] / cnt;
    __syncthreads();
    if (t < 3 * HID) {
        float s = b_ih[t];
        const float* w = W_ih + (size_t)t * DMODEL;
        for (int k = 0; k < DMODEL; k++) s += gv[k] * w[k];
        gi[t] = s;
    }
    __syncthreads();
    if (t < HID) {
        float r = 1.0f / (1.0f + __expf(-(gi[t] + b_hh[t])));
        float z = 1.0f / (1.0f + __expf(-(gi[HID + t] + b_hh[HID + t])));
        float n = tanhf(gi[2 * HID + t] + r * b_hh[2 * HID + t]);
        hh[t] = (1.0f - z) * n;
    }
    __syncthreads();
    if (t < NUM_CLASSES) {
        float s = b_fc[t];
        const float* w = W_fc + (size_t)t * HID;
        for (int k = 0; k < HID; k++) s += hh[k] * w[k];
        out[g * NUM_CLASSES + t] = s;
    }
}

// ---------------- launch ----------------
extern "C" void kernel_launch(void* const* d_in, const int* in_sizes, int n_in,
                              void* d_out, int out_size) {
    const float* x     = (const float*)d_in[0];
    const int*   ei    = (const int*)d_in[1];
    const int*   batch = (const int*)d_in[2];
    const int*   etype = (const int*)d_in[3];
    const float* Wq    = (const float*)d_in[4];
    const float* bq    = (const float*)d_in[5];
    const float* Wk    = (const float*)d_in[6];
    const float* bk    = (const float*)d_in[7];
    const float* Wv    = (const float*)d_in[8];
    const float* bv    = (const float*)d_in[9];
    const float* Eemb  = (const float*)d_in[10];
    const float* W_ih  = (const float*)d_in[11];
    const float* b_ih  = (const float*)d_in[12];
    const float* b_hh  = (const float*)d_in[14];
    const float* W_fc  = (const float*)d_in[15];
    const float* b_fc  = (const float*)d_in[16];
    float* out = (float*)d_out;

    cudaFuncSetAttribute(gemm_qkv_kernel, cudaFuncAttributeMaxDynamicSharedMemorySize, SMEM_G);

    init_kernel<<<64, 256>>>();
    hist_kernel<<<(N_EDGES + 255) / 256, 256>>>(ei);
    scan_kernel<<<1, 1024>>>();
    scatter_kernel<<<(N_EDGES + 255) / 256, 256>>>(ei);
    copyx_kernel<<<1024, 256>>>(x);
    transpose_w<<<(9 * DMODEL * DMODEL + 255) / 256, 256>>>(Wq, Wk, Wv);

    int gblocks = (N_NODES + 127) / 128;          // 235
    int ablocks = (N_NODES * 32 + 255) / 256;     // one warp per node

    for (int l = 0; l < NUM_LAYERS; l++) {
        gemm_qkv_kernel<<<gblocks, 256, SMEM_G>>>(bq + l * DMODEL, bk + l * DMODEL,
                                                  bv + l * DMODEL, l);
        attn_kernel<<<ablocks, 256>>>(ei, etype, Eemb + (size_t)l * NUM_ET * DMODEL);
    }

    pool_kernel<<<(N_NODES * (DMODEL / 4) + 255) / 256, 256>>>(batch);
    gru_kernel<<<NUM_GRAPHS, 256>>>(W_ih, b_ih, b_hh, W_fc, b_fc, out);
}

// round 10
// speedup vs baseline: 2.0684x; 1.2001x over previous
#include <cuda_runtime.h>
#include <math.h>
#include <stdint.h>

#define N_NODES   30000
#define N_EDGES   240000
#define DMODEL    256
#define HEADS     4
#define HID       64
#define NUM_LAYERS 3
#define NUM_ET    8
#define NUM_GRAPHS 64
#define NUM_CLASSES 2

// ---------------- scratch (no allocs allowed -> __device__ globals) ----------------
__device__ float g_q[N_NODES * DMODEL];
__device__ float g_k[N_NODES * DMODEL];
__device__ float g_v[N_NODES * DMODEL];
__device__ float g_x[N_NODES * DMODEL];
__device__ float g_wt[9 * DMODEL * DMODEL];   // transposed weights: [l*3+w][n][k]
__device__ int   g_cnt[N_NODES];
__device__ int   g_off[N_NODES + 1];
__device__ int   g_pos[N_NODES];
__device__ int   g_epk[N_EDGES];              // packed per-slot: src | (etype<<16)
__device__ float g_pool[NUM_GRAPHS * DMODEL];
__device__ float g_gcnt[NUM_GRAPHS];

__device__ __forceinline__ uint32_t totf32(float f) {
    uint32_t u;
    asm("cvt.rna.tf32.f32 %0, %1;" : "=r"(u) : "f"(f));
    return u;
}

// ---------------- init ----------------
__global__ void init_kernel() {
    int t = blockIdx.x * blockDim.x + threadIdx.x;
    int stride = gridDim.x * blockDim.x;
    for (int i = t; i < N_NODES; i += stride) g_cnt[i] = 0;
    for (int i = t; i < NUM_GRAPHS * DMODEL; i += stride) g_pool[i] = 0.0f;
    for (int i = t; i < NUM_GRAPHS; i += stride) g_gcnt[i] = 0.0f;
}

// ---------------- CSR build ----------------
__global__ void hist_kernel(const int* __restrict__ ei) {
    int e = blockIdx.x * blockDim.x + threadIdx.x;
    if (e >= N_EDGES) return;
    atomicAdd(&g_cnt[ei[N_EDGES + e]], 1);
}

__global__ void scan_kernel() {
    __shared__ int s_part[1024];
    const int C = (N_NODES + 1023) / 1024;
    int t = threadIdx.x;
    int base = t * C;
    int sum = 0;
    for (int i = 0; i < C; i++) { int idx = base + i; if (idx < N_NODES) sum += g_cnt[idx]; }
    s_part[t] = sum;
    __syncthreads();
    for (int off = 1; off < 1024; off <<= 1) {
        int v = (t >= off) ? s_part[t - off] : 0;
        __syncthreads();
        s_part[t] += v;
        __syncthreads();
    }
    int run = (t == 0) ? 0 : s_part[t - 1];
    for (int i = 0; i < C; i++) {
        int idx = base + i;
        if (idx < N_NODES) { g_off[idx] = run; g_pos[idx] = run; run += g_cnt[idx]; }
    }
    if (t == 1023) g_off[N_NODES] = run;
}

// scatter + fuse src/etype into one packed word per CSR slot
__global__ void scatter_kernel(const int* __restrict__ ei, const int* __restrict__ etype) {
    int e = blockIdx.x * blockDim.x + threadIdx.x;
    if (e >= N_EDGES) return;
    int dst = ei[N_EDGES + e];
    int src = ei[e];
    int et  = etype[e];
    int slot = atomicAdd(&g_pos[dst], 1);
    g_epk[slot] = src | (et << 16);
}

__global__ void copyx_kernel(const float* __restrict__ x) {
    int t = blockIdx.x * blockDim.x + threadIdx.x;
    int stride = gridDim.x * blockDim.x;
    for (int i = t; i < N_NODES * DMODEL; i += stride) g_x[i] = x[i];
}

// ---------------- weight transpose: g_wt[idx][n][k] = W[idx][k][n] ----------------
__global__ void transpose_w(const float* __restrict__ Wq, const float* __restrict__ Wk,
                            const float* __restrict__ Wv) {
    int t = blockIdx.x * blockDim.x + threadIdx.x;
    int total = 9 * DMODEL * DMODEL;
    if (t >= total) return;
    int idx = t >> 16;
    int rem = t & 65535;
    int n = rem >> 8;
    int k = rem & 255;
    int l = idx / 3, w = idx % 3;
    const float* W = (w == 0) ? Wq : ((w == 1) ? Wk : Wv);
    g_wt[t] = W[(size_t)l * DMODEL * DMODEL + (size_t)k * DMODEL + n];
}

// ---------------- tf32 mma.sync fused QKV GEMM (unchanged, known-good) ----------------
#define A_STRIDE 260
#define B_STRIDE 68
#define SMEM_G ((128 * A_STRIDE + 128 * B_STRIDE) * 4)

__device__ __forceinline__ void mma_tf32(float* c, uint32_t a0, uint32_t a1,
                                         uint32_t a2, uint32_t a3,
                                         uint32_t b0, uint32_t b1) {
    asm volatile(
        "mma.sync.aligned.m16n8k8.row.col.f32.tf32.tf32.f32 "
        "{%0,%1,%2,%3}, {%4,%5,%6,%7}, {%8,%9}, {%0,%1,%2,%3};"
        : "+f"(c[0]), "+f"(c[1]), "+f"(c[2]), "+f"(c[3])
        : "r"(a0), "r"(a1), "r"(a2), "r"(a3), "r"(b0), "r"(b1));
}

__global__ void __launch_bounds__(256, 1)
gemm_qkv_kernel(const float* __restrict__ bq, const float* __restrict__ bk,
                const float* __restrict__ bv, int l) {
    extern __shared__ float smem[];
    float* sA = smem;                       // [128][A_STRIDE]
    float* sB = smem + 128 * A_STRIDE;      // [128][B_STRIDE]

    int tid = threadIdx.x;
    int wid = tid >> 5, lane = tid & 31;
    int g = lane >> 2, tig = lane & 3;
    int wm = (wid & 3) * 32;
    int wn = (wid >> 2) * 64;
    int m0 = blockIdx.x * 128;

    for (int i = tid; i < 128 * 64; i += 256) {
        int r = i >> 6;
        int c4 = (i & 63) * 4;
        float4 v = make_float4(0.f, 0.f, 0.f, 0.f);
        if (m0 + r < N_NODES) v = *(const float4*)(g_x + (size_t)(m0 + r) * DMODEL + c4);
        float4 u;
        u.x = __uint_as_float(totf32(v.x));
        u.y = __uint_as_float(totf32(v.y));
        u.z = __uint_as_float(totf32(v.z));
        u.w = __uint_as_float(totf32(v.w));
        *(float4*)(sA + r * A_STRIDE + c4) = u;
    }

    for (int w = 0; w < 3; w++) {
        const float* __restrict__ wt = g_wt + (size_t)(l * 3 + w) * DMODEL * DMODEL;
        float* __restrict__ dstp = (w == 0) ? g_q : ((w == 1) ? g_k : g_v);
        const float* __restrict__ bias = (w == 0) ? bq : ((w == 1) ? bk : bv);

        for (int nb = 0; nb < 2; nb++) {
            int n0 = nb * 128;
            float acc[2][8][4];
#pragma unroll
            for (int mi = 0; mi < 2; mi++)
#pragma unroll
                for (int ni = 0; ni < 8; ni++)
#pragma unroll
                    for (int j = 0; j < 4; j++) acc[mi][ni][j] = 0.f;

            for (int kc = 0; kc < 4; kc++) {
                __syncthreads();
                for (int i = tid; i < 128 * 16; i += 256) {
                    int nr = i >> 4;
                    int c4 = (i & 15) * 4;
                    float4 v = *(const float4*)(wt + (size_t)(n0 + nr) * DMODEL + kc * 64 + c4);
                    float4 u;
                    u.x = __uint_as_float(totf32(v.x));
                    u.y = __uint_as_float(totf32(v.y));
                    u.z = __uint_as_float(totf32(v.z));
                    u.w = __uint_as_float(totf32(v.w));
                    *(float4*)(sB + nr * B_STRIDE + c4) = u;
                }
                __syncthreads();

#pragma unroll
                for (int ks = 0; ks < 8; ks++) {
                    int kl = ks * 8;
                    int kg = kc * 64 + kl;
                    uint32_t a[2][4];
#pragma unroll
                    for (int mi = 0; mi < 2; mi++) {
                        int r0 = wm + mi * 16 + g;
                        a[mi][0] = __float_as_uint(sA[r0 * A_STRIDE + kg + tig]);
                        a[mi][1] = __float_as_uint(sA[(r0 + 8) * A_STRIDE + kg + tig]);
                        a[mi][2] = __float_as_uint(sA[r0 * A_STRIDE + kg + tig + 4]);
                        a[mi][3] = __float_as_uint(sA[(r0 + 8) * A_STRIDE + kg + tig + 4]);
                    }
                    uint32_t b[8][2];
#pragma unroll
                    for (int ni = 0; ni < 8; ni++) {
                        int nr = wn + ni * 8 + g;
                        b[ni][0] = __float_as_uint(sB[nr * B_STRIDE + kl + tig]);
                        b[ni][1] = __float_as_uint(sB[nr * B_STRIDE + kl + tig + 4]);
                    }
#pragma unroll
                    for (int mi = 0; mi < 2; mi++)
#pragma unroll
                        for (int ni = 0; ni < 8; ni++)
                            mma_tf32(acc[mi][ni], a[mi][0], a[mi][1], a[mi][2], a[mi][3],
                                     b[ni][0], b[ni][1]);
                }
            }

#pragma unroll
            for (int mi = 0; mi < 2; mi++) {
                int r0 = m0 + wm + mi * 16 + g;
                int r1 = r0 + 8;
#pragma unroll
                for (int ni = 0; ni < 8; ni++) {
                    int col = n0 + wn + ni * 8 + tig * 2;
                    float b0 = bias[col], b1 = bias[col + 1];
                    if (r0 < N_NODES) {
                        float2 o0 = make_float2(acc[mi][ni][0] + b0, acc[mi][ni][1] + b1);
                        *(float2*)(dstp + (size_t)r0 * DMODEL + col) = o0;
                    }
                    if (r1 < N_NODES) {
                        float2 o1 = make_float2(acc[mi][ni][2] + b0, acc[mi][ni][3] + b1);
                        *(float2*)(dstp + (size_t)r1 * DMODEL + col) = o1;
                    }
                }
            }
        }
    }
}

// ---------------- attention gather: warp per node; 8-lane group per head ----------------
// lane = 8*g + li : head g, dims 64*g + 8*li .. +7 (2 x float4 per row)
__global__ void attn_kernel(const float* __restrict__ Eemb_l) {
    __shared__ float s_ete[NUM_ET * DMODEL];
    for (int i = threadIdx.x; i < NUM_ET * DMODEL; i += blockDim.x)
        s_ete[i] = Eemb_l[i];
    __syncthreads();

    int gw = (blockIdx.x * blockDim.x + threadIdx.x) >> 5;
    int lane = threadIdx.x & 31;
    if (gw >= N_NODES) return;
    int node = gw;
    int g = lane >> 3, li = lane & 7;
    int dbase = g * 64 + li * 8;

    float4 q0 = *(const float4*)(g_q + (size_t)node * DMODEL + dbase);
    float4 q1 = *(const float4*)(g_q + (size_t)node * DMODEL + dbase + 4);

    int beg = g_off[node], end = g_off[node + 1];
    float m = -INFINITY, den = 0.f;
    float4 acc0 = make_float4(0.f, 0.f, 0.f, 0.f);
    float4 acc1 = make_float4(0.f, 0.f, 0.f, 0.f);
    const float scale = 0.125f;  // 1/sqrt(64)

    int pk = (beg < end) ? g_epk[beg] : 0;
    for (int t = beg; t < end; t++) {
        int pknext = (t + 1 < end) ? g_epk[t + 1] : 0;
        int src = pk & 0xFFFF;
        int et = pk >> 16;
        const float* kb = g_k + (size_t)src * DMODEL + dbase;
        const float* vb = g_v + (size_t)src * DMODEL + dbase;
        const float* eb = s_ete + et * DMODEL + dbase;

        float4 k0 = *(const float4*)(kb);
        float4 k1 = *(const float4*)(kb + 4);
        float4 v0 = *(const float4*)(vb);
        float4 v1 = *(const float4*)(vb + 4);
        float4 e0 = *(const float4*)(eb);
        float4 e1 = *(const float4*)(eb + 4);
        pk = pknext;

        // k + ete, dot with q (8 dims per lane)
        float s = q0.x * (k0.x + e0.x) + q0.y * (k0.y + e0.y)
                + q0.z * (k0.z + e0.z) + q0.w * (k0.w + e0.w)
                + q1.x * (k1.x + e1.x) + q1.y * (k1.y + e1.y)
                + q1.z * (k1.z + e1.z) + q1.w * (k1.w + e1.w);
        // reduce over the 8-lane group (xor 1,2,4 stays inside the group)
        s += __shfl_xor_sync(0xffffffffu, s, 1);
        s += __shfl_xor_sync(0xffffffffu, s, 2);
        s += __shfl_xor_sync(0xffffffffu, s, 4);
        s *= scale;

        float nm = fmaxf(m, s);
        float sc = __expf(m - nm);
        float p = __expf(s - nm);
        den = den * sc + p;
        m = nm;

        acc0.x = acc0.x * sc + p * (v0.x + e0.x);
        acc0.y = acc0.y * sc + p * (v0.y + e0.y);
        acc0.z = acc0.z * sc + p * (v0.z + e0.z);
        acc0.w = acc0.w * sc + p * (v0.w + e0.w);
        acc1.x = acc1.x * sc + p * (v1.x + e1.x);
        acc1.y = acc1.y * sc + p * (v1.y + e1.y);
        acc1.z = acc1.z * sc + p * (v1.z + e1.z);
        acc1.w = acc1.w * sc + p * (v1.w + e1.w);
    }

    float inv = 1.0f / (den + 1e-16f);
    float o[8] = { acc0.x * inv, acc0.y * inv, acc0.z * inv, acc0.w * inv,
                   acc1.x * inv, acc1.y * inv, acc1.z * inv, acc1.w * inv };
#pragma unroll
    for (int j = 0; j < 8; j++) o[j] = (o[j] > 0.f) ? o[j] : expm1f(o[j]);
    *(float4*)(g_x + (size_t)node * DMODEL + dbase)     = make_float4(o[0], o[1], o[2], o[3]);
    *(float4*)(g_x + (size_t)node * DMODEL + dbase + 4) = make_float4(o[4], o[5], o[6], o[7]);
}

// ---------------- global mean pool: run-length accumulate (batch is sorted) ----------------
#define POOL_NPB 64
__global__ void pool_kernel(const int* __restrict__ batch) {
    __shared__ int s_b[POOL_NPB];
    int d = threadIdx.x;               // dim 0..255
    int n0 = blockIdx.x * POOL_NPB;
    int nend = min(n0 + POOL_NPB, N_NODES);
    int cnt = nend - n0;
    if (d < cnt) s_b[d] = batch[n0 + d];
    __syncthreads();

    int curb = s_b[0];
    float run = 0.f;
    for (int i = 0; i < cnt; i++) {
        int b = s_b[i];
        if (b != curb) {
            atomicAdd(&g_pool[curb * DMODEL + d], run);
            run = 0.f;
            curb = b;
        }
        run += g_x[(size_t)(n0 + i) * DMODEL + d];
    }
    atomicAdd(&g_pool[curb * DMODEL + d], run);

    if (d == 0) {
        int cb = s_b[0];
        float c = 0.f;
        for (int i = 0; i < cnt; i++) {
            if (s_b[i] != cb) { atomicAdd(&g_gcnt[cb], c); c = 0.f; cb = s_b[i]; }
            c += 1.0f;
        }
        atomicAdd(&g_gcnt[cb], c);
    }
}

// ---------------- GRU + FC ----------------
__global__ void gru_kernel(const float* __restrict__ W_ih,
                           const float* __restrict__ b_ih,
                           const float* __restrict__ b_hh,
                           const float* __restrict__ W_fc,
                           const float* __restrict__ b_fc,
                           float* __restrict__ out) {
    __shared__ float gv[DMODEL];
    __shared__ float gi[3 * HID];
    __shared__ float hh[HID];
    int g = blockIdx.x, t = threadIdx.x;
    float cnt = fmaxf(g_gcnt[g], 1.0f);
    if (t < DMODEL) gv[t] = g_pool[g * DMODEL + t] / cnt;
    __syncthreads();
    if (t < 3 * HID) {
        float s = b_ih[t];
        const float* w = W_ih + (size_t)t * DMODEL;
        for (int k = 0; k < DMODEL; k++) s += gv[k] * w[k];
        gi[t] = s;
    }
    __syncthreads();
    if (t < HID) {
        float r = 1.0f / (1.0f + __expf(-(gi[t] + b_hh[t])));
        float z = 1.0f / (1.0f + __expf(-(gi[HID + t] + b_hh[HID + t])));
        float n = tanhf(gi[2 * HID + t] + r * b_hh[2 * HID + t]);
        hh[t] = (1.0f - z) * n;
    }
    __syncthreads();
    if (t < NUM_CLASSES) {
        float s = b_fc[t];
        const float* w = W_fc + (size_t)t * HID;
        for (int k = 0; k < HID; k++) s += hh[k] * w[k];
        out[g * NUM_CLASSES + t] = s;
    }
}

// ---------------- launch ----------------
extern "C" void kernel_launch(void* const* d_in, const int* in_sizes, int n_in,
                              void* d_out, int out_size) {
    const float* x     = (const float*)d_in[0];
    const int*   ei    = (const int*)d_in[1];
    const int*   batch = (const int*)d_in[2];
    const int*   etype = (const int*)d_in[3];
    const float* Wq    = (const float*)d_in[4];
    const float* bq    = (const float*)d_in[5];
    const float* Wk    = (const float*)d_in[6];
    const float* bk    = (const float*)d_in[7];
    const float* Wv    = (const float*)d_in[8];
    const float* bv    = (const float*)d_in[9];
    const float* Eemb  = (const float*)d_in[10];
    const float* W_ih  = (const float*)d_in[11];
    const float* b_ih  = (const float*)d_in[12];
    const float* b_hh  = (const float*)d_in[14];
    const float* W_fc  = (const float*)d_in[15];
    const float* b_fc  = (const float*)d_in[16];
    float* out = (float*)d_out;

    cudaFuncSetAttribute(gemm_qkv_kernel, cudaFuncAttributeMaxDynamicSharedMemorySize, SMEM_G);

    init_kernel<<<64, 256>>>();
    hist_kernel<<<(N_EDGES + 255) / 256, 256>>>(ei);
    scan_kernel<<<1, 1024>>>();
    scatter_kernel<<<(N_EDGES + 255) / 256, 256>>>(ei, etype);
    copyx_kernel<<<1024, 256>>>(x);
    transpose_w<<<(9 * DMODEL * DMODEL + 255) / 256, 256>>>(Wq, Wk, Wv);

    int gblocks = (N_NODES + 127) / 128;          // 235
    int ablocks = (N_NODES * 32 + 255) / 256;     // one warp per node

    for (int l = 0; l < NUM_LAYERS; l++) {
        gemm_qkv_kernel<<<gblocks, 256, SMEM_G>>>(bq + l * DMODEL, bk + l * DMODEL,
                                                  bv + l * DMODEL, l);
        attn_kernel<<<ablocks, 256>>>(Eemb + (size_t)l * NUM_ET * DMODEL);
    }

    pool_kernel<<<(N_NODES + POOL_NPB - 1) / POOL_NPB, 256>>>(batch);
    gru_kernel<<<NUM_GRAPHS, 256>>>(W_ih, b_ih, b_hh, W_fc, b_fc, out);
}

// round 15
// speedup vs baseline: 2.0982x; 1.0144x over previous
#include <cuda_runtime.h>
#include <math.h>
#include <stdint.h>

#define N_NODES   30000
#define N_EDGES   240000
#define DMODEL    256
#define HEADS     4
#define HID       64
#define NUM_LAYERS 3
#define NUM_ET    8
#define NUM_GRAPHS 64
#define NUM_CLASSES 2

// ---------------- scratch (no allocs allowed -> __device__ globals) ----------------
__device__ float g_q[N_NODES * DMODEL];
__device__ float g_k[N_NODES * DMODEL];
__device__ float g_v[N_NODES * DMODEL];
__device__ float g_x[N_NODES * DMODEL];
__device__ float g_wt[9 * DMODEL * DMODEL];   // transposed weights: [l*3+w][n][k]
__device__ int   g_cnt[N_NODES];
__device__ int   g_off[N_NODES + 1];
__device__ int   g_pos[N_NODES];
__device__ int   g_epk[N_EDGES];              // packed per-slot: src | (etype<<16)
__device__ float g_pool[NUM_GRAPHS * DMODEL];
__device__ float g_gcnt[NUM_GRAPHS];

__device__ __forceinline__ uint32_t totf32(float f) {
    uint32_t u;
    asm("cvt.rna.tf32.f32 %0, %1;" : "=r"(u) : "f"(f));
    return u;
}

// ---------------- init ----------------
__global__ void init_kernel() {
    int t = blockIdx.x * blockDim.x + threadIdx.x;
    int stride = gridDim.x * blockDim.x;
    for (int i = t; i < N_NODES; i += stride) g_cnt[i] = 0;
    for (int i = t; i < NUM_GRAPHS * DMODEL; i += stride) g_pool[i] = 0.0f;
    for (int i = t; i < NUM_GRAPHS; i += stride) g_gcnt[i] = 0.0f;
}

// ---------------- CSR build ----------------
__global__ void hist_kernel(const int* __restrict__ ei) {
    int e = blockIdx.x * blockDim.x + threadIdx.x;
    if (e >= N_EDGES) return;
    atomicAdd(&g_cnt[ei[N_EDGES + e]], 1);
}

__global__ void scan_kernel() {
    __shared__ int s_part[1024];
    const int C = (N_NODES + 1023) / 1024;
    int t = threadIdx.x;
    int base = t * C;
    int sum = 0;
    for (int i = 0; i < C; i++) { int idx = base + i; if (idx < N_NODES) sum += g_cnt[idx]; }
    s_part[t] = sum;
    __syncthreads();
    for (int off = 1; off < 1024; off <<= 1) {
        int v = (t >= off) ? s_part[t - off] : 0;
        __syncthreads();
        s_part[t] += v;
        __syncthreads();
    }
    int run = (t == 0) ? 0 : s_part[t - 1];
    for (int i = 0; i < C; i++) {
        int idx = base + i;
        if (idx < N_NODES) { g_off[idx] = run; g_pos[idx] = run; run += g_cnt[idx]; }
    }
    if (t == 1023) g_off[N_NODES] = run;
}

// scatter + fuse src/etype into one packed word per CSR slot
__global__ void scatter_kernel(const int* __restrict__ ei, const int* __restrict__ etype) {
    int e = blockIdx.x * blockDim.x + threadIdx.x;
    if (e >= N_EDGES) return;
    int dst = ei[N_EDGES + e];
    int src = ei[e];
    int et  = etype[e];
    int slot = atomicAdd(&g_pos[dst], 1);
    g_epk[slot] = src | (et << 16);
}

// ---------------- weight transpose: g_wt[idx][n][k] = W[idx][k][n] ----------------
__global__ void transpose_w(const float* __restrict__ Wq, const float* __restrict__ Wk,
                            const float* __restrict__ Wv) {
    int t = blockIdx.x * blockDim.x + threadIdx.x;
    int total = 9 * DMODEL * DMODEL;
    if (t >= total) return;
    int idx = t >> 16;
    int rem = t & 65535;
    int n = rem >> 8;
    int k = rem & 255;
    int l = idx / 3, w = idx % 3;
    const float* W = (w == 0) ? Wq : ((w == 1) ? Wk : Wv);
    g_wt[t] = W[(size_t)l * DMODEL * DMODEL + (size_t)k * DMODEL + n];
}

// ---------------- tf32 mma.sync fused QKV GEMM ----------------
#define A_STRIDE 260
#define B_STRIDE 68
#define SMEM_G ((128 * A_STRIDE + 128 * B_STRIDE) * 4)

__device__ __forceinline__ void mma_tf32(float* c, uint32_t a0, uint32_t a1,
                                         uint32_t a2, uint32_t a3,
                                         uint32_t b0, uint32_t b1) {
    asm volatile(
        "mma.sync.aligned.m16n8k8.row.col.f32.tf32.tf32.f32 "
        "{%0,%1,%2,%3}, {%4,%5,%6,%7}, {%8,%9}, {%0,%1,%2,%3};"
        : "+f"(c[0]), "+f"(c[1]), "+f"(c[2]), "+f"(c[3])
        : "r"(a0), "r"(a1), "r"(a2), "r"(a3), "r"(b0), "r"(b1));
}

__global__ void __launch_bounds__(256, 1)
gemm_qkv_kernel(const float* __restrict__ xin,
                const float* __restrict__ bq, const float* __restrict__ bk,
                const float* __restrict__ bv, int l) {
    extern __shared__ float smem[];
    float* sA = smem;                       // [128][A_STRIDE]
    float* sB = smem + 128 * A_STRIDE;      // [128][B_STRIDE]

    // device-side select: layer 0 reads harness input, later layers read g_x
    const float* __restrict__ Asrc = (l == 0) ? xin : (const float*)g_x;

    int tid = threadIdx.x;
    int wid = tid >> 5, lane = tid & 31;
    int g = lane >> 2, tig = lane & 3;
    int wm = (wid & 3) * 32;
    int wn = (wid >> 2) * 64;
    int m0 = blockIdx.x * 128;

    for (int i = tid; i < 128 * 64; i += 256) {
        int r = i >> 6;
        int c4 = (i & 63) * 4;
        float4 v = make_float4(0.f, 0.f, 0.f, 0.f);
        if (m0 + r < N_NODES) v = *(const float4*)(Asrc + (size_t)(m0 + r) * DMODEL + c4);
        float4 u;
        u.x = __uint_as_float(totf32(v.x));
        u.y = __uint_as_float(totf32(v.y));
        u.z = __uint_as_float(totf32(v.z));
        u.w = __uint_as_float(totf32(v.w));
        *(float4*)(sA + r * A_STRIDE + c4) = u;
    }

    for (int w = 0; w < 3; w++) {
        const float* __restrict__ wt = g_wt + (size_t)(l * 3 + w) * DMODEL * DMODEL;
        float* __restrict__ dstp = (w == 0) ? g_q : ((w == 1) ? g_k : g_v);
        const float* __restrict__ bias = (w == 0) ? bq : ((w == 1) ? bk : bv);

        for (int nb = 0; nb < 2; nb++) {
            int n0 = nb * 128;
            float acc[2][8][4];
#pragma unroll
            for (int mi = 0; mi < 2; mi++)
#pragma unroll
                for (int ni = 0; ni < 8; ni++)
#pragma unroll
                    for (int j = 0; j < 4; j++) acc[mi][ni][j] = 0.f;

            for (int kc = 0; kc < 4; kc++) {
                __syncthreads();
                for (int i = tid; i < 128 * 16; i += 256) {
                    int nr = i >> 4;
                    int c4 = (i & 15) * 4;
                    float4 v = *(const float4*)(wt + (size_t)(n0 + nr) * DMODEL + kc * 64 + c4);
                    float4 u;
                    u.x = __uint_as_float(totf32(v.x));
                    u.y = __uint_as_float(totf32(v.y));
                    u.z = __uint_as_float(totf32(v.z));
                    u.w = __uint_as_float(totf32(v.w));
                    *(float4*)(sB + nr * B_STRIDE + c4) = u;
                }
                __syncthreads();

#pragma unroll
                for (int ks = 0; ks < 8; ks++) {
                    int kl = ks * 8;
                    int kg = kc * 64 + kl;
                    uint32_t a[2][4];
#pragma unroll
                    for (int mi = 0; mi < 2; mi++) {
                        int r0 = wm + mi * 16 + g;
                        a[mi][0] = __float_as_uint(sA[r0 * A_STRIDE + kg + tig]);
                        a[mi][1] = __float_as_uint(sA[(r0 + 8) * A_STRIDE + kg + tig]);
                        a[mi][2] = __float_as_uint(sA[r0 * A_STRIDE + kg + tig + 4]);
                        a[mi][3] = __float_as_uint(sA[(r0 + 8) * A_STRIDE + kg + tig + 4]);
                    }
                    uint32_t b[8][2];
#pragma unroll
                    for (int ni = 0; ni < 8; ni++) {
                        int nr = wn + ni * 8 + g;
                        b[ni][0] = __float_as_uint(sB[nr * B_STRIDE + kl + tig]);
                        b[ni][1] = __float_as_uint(sB[nr * B_STRIDE + kl + tig + 4]);
                    }
#pragma unroll
                    for (int mi = 0; mi < 2; mi++)
#pragma unroll
                        for (int ni = 0; ni < 8; ni++)
                            mma_tf32(acc[mi][ni], a[mi][0], a[mi][1], a[mi][2], a[mi][3],
                                     b[ni][0], b[ni][1]);
                }
            }

#pragma unroll
            for (int mi = 0; mi < 2; mi++) {
                int r0 = m0 + wm + mi * 16 + g;
                int r1 = r0 + 8;
#pragma unroll
                for (int ni = 0; ni < 8; ni++) {
                    int col = n0 + wn + ni * 8 + tig * 2;
                    float b0 = bias[col], b1 = bias[col + 1];
                    if (r0 < N_NODES) {
                        float2 o0 = make_float2(acc[mi][ni][0] + b0, acc[mi][ni][1] + b1);
                        *(float2*)(dstp + (size_t)r0 * DMODEL + col) = o0;
                    }
                    if (r1 < N_NODES) {
                        float2 o1 = make_float2(acc[mi][ni][2] + b0, acc[mi][ni][3] + b1);
                        *(float2*)(dstp + (size_t)r1 * DMODEL + col) = o1;
                    }
                }
            }
        }
    }
}

// ---------------- attention: warp/node, 8-lane group/head, 2-edge pipelined ----------------
__global__ void attn_kernel(const float* __restrict__ Eemb_l) {
    __shared__ float s_ete[NUM_ET * DMODEL];
    for (int i = threadIdx.x; i < NUM_ET * DMODEL; i += blockDim.x)
        s_ete[i] = Eemb_l[i];
    __syncthreads();

    int gw = (blockIdx.x * blockDim.x + threadIdx.x) >> 5;
    int lane = threadIdx.x & 31;
    if (gw >= N_NODES) return;
    int node = gw;
    int g = lane >> 3, li = lane & 7;
    int dbase = g * 64 + li * 8;

    float4 q0 = *(const float4*)(g_q + (size_t)node * DMODEL + dbase);
    float4 q1 = *(const float4*)(g_q + (size_t)node * DMODEL + dbase + 4);

    int beg = g_off[node], end = g_off[node + 1];
    float m = -INFINITY, den = 0.f;
    float4 acc0 = make_float4(0.f, 0.f, 0.f, 0.f);
    float4 acc1 = make_float4(0.f, 0.f, 0.f, 0.f);
    const float scale = 0.125f;  // 1/sqrt(64)

    int t = beg;
    for (; t + 1 < end; t += 2) {
        int pkA = g_epk[t];
        int pkB = g_epk[t + 1];
        int srcA = pkA & 0xFFFF, etA = pkA >> 16;
        int srcB = pkB & 0xFFFF, etB = pkB >> 16;
        const float* kbA = g_k + (size_t)srcA * DMODEL + dbase;
        const float* vbA = g_v + (size_t)srcA * DMODEL + dbase;
        const float* ebA = s_ete + etA * DMODEL + dbase;
        const float* kbB = g_k + (size_t)srcB * DMODEL + dbase;
        const float* vbB = g_v + (size_t)srcB * DMODEL + dbase;
        const float* ebB = s_ete + etB * DMODEL + dbase;

        float4 kA0 = *(const float4*)(kbA);
        float4 kA1 = *(const float4*)(kbA + 4);
        float4 kB0 = *(const float4*)(kbB);
        float4 kB1 = *(const float4*)(kbB + 4);
        float4 vA0 = *(const float4*)(vbA);
        float4 vA1 = *(const float4*)(vbA + 4);
        float4 vB0 = *(const float4*)(vbB);
        float4 vB1 = *(const float4*)(vbB + 4);
        float4 eA0 = *(const float4*)(ebA);
        float4 eA1 = *(const float4*)(ebA + 4);
        float4 eB0 = *(const float4*)(ebB);
        float4 eB1 = *(const float4*)(ebB + 4);

        float sA = q0.x * (kA0.x + eA0.x) + q0.y * (kA0.y + eA0.y)
                 + q0.z * (kA0.z + eA0.z) + q0.w * (kA0.w + eA0.w)
                 + q1.x * (kA1.x + eA1.x) + q1.y * (kA1.y + eA1.y)
                 + q1.z * (kA1.z + eA1.z) + q1.w * (kA1.w + eA1.w);
        float sB = q0.x * (kB0.x + eB0.x) + q0.y * (kB0.y + eB0.y)
                 + q0.z * (kB0.z + eB0.z) + q0.w * (kB0.w + eB0.w)
                 + q1.x * (kB1.x + eB1.x) + q1.y * (kB1.y + eB1.y)
                 + q1.z * (kB1.z + eB1.z) + q1.w * (kB1.w + eB1.w);

        sA += __shfl_xor_sync(0xffffffffu, sA, 1);
        sB += __shfl_xor_sync(0xffffffffu, sB, 1);
        sA += __shfl_xor_sync(0xffffffffu, sA, 2);
        sB += __shfl_xor_sync(0xffffffffu, sB, 2);
        sA += __shfl_xor_sync(0xffffffffu, sA, 4);
        sB += __shfl_xor_sync(0xffffffffu, sB, 4);
        sA *= scale;
        sB *= scale;

        float nm = fmaxf(m, fmaxf(sA, sB));
        float sc = __expf(m - nm);
        float pA = __expf(sA - nm);
        float pB = __expf(sB - nm);
        den = den * sc + pA + pB;
        m = nm;

        acc0.x = acc0.x * sc + pA * (vA0.x + eA0.x) + pB * (vB0.x + eB0.x);
        acc0.y = acc0.y * sc + pA * (vA0.y + eA0.y) + pB * (vB0.y + eB0.y);
        acc0.z = acc0.z * sc + pA * (vA0.z + eA0.z) + pB * (vB0.z + eB0.z);
        acc0.w = acc0.w * sc + pA * (vA0.w + eA0.w) + pB * (vB0.w + eB0.w);
        acc1.x = acc1.x * sc + pA * (vA1.x + eA1.x) + pB * (vB1.x + eB1.x);
        acc1.y = acc1.y * sc + pA * (vA1.y + eA1.y) + pB * (vB1.y + eB1.y);
        acc1.z = acc1.z * sc + pA * (vA1.z + eA1.z) + pB * (vB1.z + eB1.z);
        acc1.w = acc1.w * sc + pA * (vA1.w + eA1.w) + pB * (vB1.w + eB1.w);
    }
    if (t < end) {
        int pk = g_epk[t];
        int src = pk & 0xFFFF, et = pk >> 16;
        const float* kb = g_k + (size_t)src * DMODEL + dbase;
        const float* vb = g_v + (size_t)src * DMODEL + dbase;
        const float* eb = s_ete + et * DMODEL + dbase;
        float4 k0 = *(const float4*)(kb);
        float4 k1 = *(const float4*)(kb + 4);
        float4 v0 = *(const float4*)(vb);
        float4 v1 = *(const float4*)(vb + 4);
        float4 e0 = *(const float4*)(eb);
        float4 e1 = *(const float4*)(eb + 4);
        float s = q0.x * (k0.x + e0.x) + q0.y * (k0.y + e0.y)
                + q0.z * (k0.z + e0.z) + q0.w * (k0.w + e0.w)
                + q1.x * (k1.x + e1.x) + q1.y * (k1.y + e1.y)
                + q1.z * (k1.z + e1.z) + q1.w * (k1.w + e1.w);
        s += __shfl_xor_sync(0xffffffffu, s, 1);
        s += __shfl_xor_sync(0xffffffffu, s, 2);
        s += __shfl_xor_sync(0xffffffffu, s, 4);
        s *= scale;
        float nm = fmaxf(m, s);
        float sc = __expf(m - nm);
        float p = __expf(s - nm);
        den = den * sc + p;
        m = nm;
        acc0.x = acc0.x * sc + p * (v0.x + e0.x);
        acc0.y = acc0.y * sc + p * (v0.y + e0.y);
        acc0.z = acc0.z * sc + p * (v0.z + e0.z);
        acc0.w = acc0.w * sc + p * (v0.w + e0.w);
        acc1.x = acc1.x * sc + p * (v1.x + e1.x);
        acc1.y = acc1.y * sc + p * (v1.y + e1.y);
        acc1.z = acc1.z * sc + p * (v1.z + e1.z);
        acc1.w = acc1.w * sc + p * (v1.w + e1.w);
    }

    float inv = 1.0f / (den + 1e-16f);
    float o[8] = { acc0.x * inv, acc0.y * inv, acc0.z * inv, acc0.w * inv,
                   acc1.x * inv, acc1.y * inv, acc1.z * inv, acc1.w * inv };
#pragma unroll
    for (int j = 0; j < 8; j++) o[j] = (o[j] > 0.f) ? o[j] : expm1f(o[j]);
    *(float4*)(g_x + (size_t)node * DMODEL + dbase)     = make_float4(o[0], o[1], o[2], o[3]);
    *(float4*)(g_x + (size_t)node * DMODEL + dbase + 4) = make_float4(o[4], o[5], o[6], o[7]);
}

// ---------------- global mean pool: run-length accumulate (batch is sorted) ----------------
#define POOL_NPB 64
__global__ void pool_kernel(const int* __restrict__ batch) {
    __shared__ int s_b[POOL_NPB];
    int d = threadIdx.x;               // dim 0..255
    int n0 = blockIdx.x * POOL_NPB;
    int nend = min(n0 + POOL_NPB, N_NODES);
    int cnt = nend - n0;
    if (d < cnt) s_b[d] = batch[n0 + d];
    __syncthreads();

    int curb = s_b[0];
    float run = 0.f;
    for (int i = 0; i < cnt; i++) {
        int b = s_b[i];
        if (b != curb) {
            atomicAdd(&g_pool[curb * DMODEL + d], run);
            run = 0.f;
            curb = b;
        }
        run += g_x[(size_t)(n0 + i) * DMODEL + d];
    }
    atomicAdd(&g_pool[curb * DMODEL + d], run);

    if (d == 0) {
        int cb = s_b[0];
        float c = 0.f;
        for (int i = 0; i < cnt; i++) {
            if (s_b[i] != cb) { atomicAdd(&g_gcnt[cb], c); c = 0.f; cb = s_b[i]; }
            c += 1.0f;
        }
        atomicAdd(&g_gcnt[cb], c);
    }
}

// ---------------- GRU + FC ----------------
__global__ void gru_kernel(const float* __restrict__ W_ih,
                           const float* __restrict__ b_ih,
                           const float* __restrict__ b_hh,
                           const float* __restrict__ W_fc,
                           const float* __restrict__ b_fc,
                           float* __restrict__ out) {
    __shared__ float gv[DMODEL];
    __shared__ float gi[3 * HID];
    __shared__ float hh[HID];
    int g = blockIdx.x, t = threadIdx.x;
    float cnt = fmaxf(g_gcnt[g], 1.0f);
    if (t < DMODEL) gv[t] = g_pool[g * DMODEL + t] / cnt;
    __syncthreads();
    if (t < 3 * HID) {
        float s = b_ih[t];
        const float* w = W_ih + (size_t)t * DMODEL;
        for (int k = 0; k < DMODEL; k++) s += gv[k] * w[k];
        gi[t] = s;
    }
    __syncthreads();
    if (t < HID) {
        float r = 1.0f / (1.0f + __expf(-(gi[t] + b_hh[t])));
        float z = 1.0f / (1.0f + __expf(-(gi[HID + t] + b_hh[HID + t])));
        float n = tanhf(gi[2 * HID + t] + r * b_hh[2 * HID + t]);
        hh[t] = (1.0f - z) * n;
    }
    __syncthreads();
    if (t < NUM_CLASSES) {
        float s = b_fc[t];
        const float* w = W_fc + (size_t)t * HID;
        for (int k = 0; k < HID; k++) s += hh[k] * w[k];
        out[g * NUM_CLASSES + t] = s;
    }
}

// ---------------- launch ----------------
extern "C" void kernel_launch(void* const* d_in, const int* in_sizes, int n_in,
                              void* d_out, int out_size) {
    const float* x     = (const float*)d_in[0];
    const int*   ei    = (const int*)d_in[1];
    const int*   batch = (const int*)d_in[2];
    const int*   etype = (const int*)d_in[3];
    const float* Wq    = (const float*)d_in[4];
    const float* bq    = (const float*)d_in[5];
    const float* Wk    = (const float*)d_in[6];
    const float* bk    = (const float*)d_in[7];
    const float* Wv    = (const float*)d_in[8];
    const float* bv    = (const float*)d_in[9];
    const float* Eemb  = (const float*)d_in[10];
    const float* W_ih  = (const float*)d_in[11];
    const float* b_ih  = (const float*)d_in[12];
    const float* b_hh  = (const float*)d_in[14];
    const float* W_fc  = (const float*)d_in[15];
    const float* b_fc  = (const float*)d_in[16];
    float* out = (float*)d_out;

    cudaFuncSetAttribute(gemm_qkv_kernel, cudaFuncAttributeMaxDynamicSharedMemorySize, SMEM_G);

    init_kernel<<<64, 256>>>();
    hist_kernel<<<(N_EDGES + 255) / 256, 256>>>(ei);
    scan_kernel<<<1, 1024>>>();
    scatter_kernel<<<(N_EDGES + 255) / 256, 256>>>(ei, etype);
    transpose_w<<<(9 * DMODEL * DMODEL + 255) / 256, 256>>>(Wq, Wk, Wv);

    int gblocks = (N_NODES + 127) / 128;          // 235
    int ablocks = (N_NODES * 32 + 255) / 256;     // one warp per node

    for (int l = 0; l < NUM_LAYERS; l++) {
        gemm_qkv_kernel<<<gblocks, 256, SMEM_G>>>(x, bq + l * DMODEL, bk + l * DMODEL,
                                                  bv + l * DMODEL, l);
        attn_kernel<<<ablocks, 256>>>(Eemb + (size_t)l * NUM_ET * DMODEL);
    }

    pool_kernel<<<(N_NODES + POOL_NPB - 1) / POOL_NPB, 256>>>(batch);
    gru_kernel<<<NUM_GRAPHS, 256>>>(W_ih, b_ih, b_hh, W_fc, b_fc, out);
}

// round 16
// speedup vs baseline: 2.9141x; 1.3889x over previous
#include <cuda_runtime.h>
#include <cuda_fp16.h>
#include <math.h>
#include <stdint.h>

#define N_NODES   30000
#define N_EDGES   240000
#define DMODEL    256
#define HEADS     4
#define HID       64
#define NUM_LAYERS 3
#define NUM_ET    8
#define NUM_GRAPHS 64
#define NUM_CLASSES 2

// ---------------- scratch (no allocs allowed -> __device__ globals) ----------------
__device__ float  g_q[N_NODES * DMODEL];
__device__ float  g_k[N_NODES * DMODEL];
__device__ float  g_v[N_NODES * DMODEL];
__device__ float  g_x[N_NODES * DMODEL];
__device__ __half g_wth[9 * DMODEL * DMODEL];  // transposed half weights: [l*3+w][n][k]
__device__ int    g_cnt[N_NODES];
__device__ int    g_off[N_NODES + 1];
__device__ int    g_pos[N_NODES];
__device__ int    g_epk[N_EDGES];              // packed per-slot: src | (etype<<16)
__device__ float  g_pool[NUM_GRAPHS * DMODEL];
__device__ float  g_gcnt[NUM_GRAPHS];

// ---------------- init ----------------
__global__ void init_kernel() {
    int t = blockIdx.x * blockDim.x + threadIdx.x;
    int stride = gridDim.x * blockDim.x;
    for (int i = t; i < N_NODES; i += stride) g_cnt[i] = 0;
    for (int i = t; i < NUM_GRAPHS * DMODEL; i += stride) g_pool[i] = 0.0f;
    for (int i = t; i < NUM_GRAPHS; i += stride) g_gcnt[i] = 0.0f;
}

// ---------------- CSR build ----------------
__global__ void hist_kernel(const int* __restrict__ ei) {
    int e = blockIdx.x * blockDim.x + threadIdx.x;
    if (e >= N_EDGES) return;
    atomicAdd(&g_cnt[ei[N_EDGES + e]], 1);
}

__global__ void scan_kernel() {
    __shared__ int s_part[1024];
    const int C = (N_NODES + 1023) / 1024;
    int t = threadIdx.x;
    int base = t * C;
    int sum = 0;
    for (int i = 0; i < C; i++) { int idx = base + i; if (idx < N_NODES) sum += g_cnt[idx]; }
    s_part[t] = sum;
    __syncthreads();
    for (int off = 1; off < 1024; off <<= 1) {
        int v = (t >= off) ? s_part[t - off] : 0;
        __syncthreads();
        s_part[t] += v;
        __syncthreads();
    }
    int run = (t == 0) ? 0 : s_part[t - 1];
    for (int i = 0; i < C; i++) {
        int idx = base + i;
        if (idx < N_NODES) { g_off[idx] = run; g_pos[idx] = run; run += g_cnt[idx]; }
    }
    if (t == 1023) g_off[N_NODES] = run;
}

__global__ void scatter_kernel(const int* __restrict__ ei, const int* __restrict__ etype) {
    int e = blockIdx.x * blockDim.x + threadIdx.x;
    if (e >= N_EDGES) return;
    int dst = ei[N_EDGES + e];
    int src = ei[e];
    int et  = etype[e];
    int slot = atomicAdd(&g_pos[dst], 1);
    g_epk[slot] = src | (et << 16);
}

// ---------------- weight transpose + fp16 convert: g_wth[idx][n][k] = h(W[idx][k][n]) ----
__global__ void transpose_w(const float* __restrict__ Wq, const float* __restrict__ Wk,
                            const float* __restrict__ Wv) {
    int t = blockIdx.x * blockDim.x + threadIdx.x;
    int total = 9 * DMODEL * DMODEL;
    if (t >= total) return;
    int idx = t >> 16;
    int rem = t & 65535;
    int n = rem >> 8;
    int k = rem & 255;
    int l = idx / 3, w = idx % 3;
    const float* W = (w == 0) ? Wq : ((w == 1) ? Wk : Wv);
    g_wth[t] = __float2half_rn(W[(size_t)l * DMODEL * DMODEL + (size_t)k * DMODEL + n]);
}

// ---------------- fp16 mma.sync fused QKV GEMM ----------------
// CTA 128(M)x128(N) per pass (2 passes for N=256), 8 warps 4(m)x2(n), warp tile 32x64.
// A resident in SMEM as half [128][264]; B streamed in K=64 half chunks [128][72].
// 84KB smem -> 2 CTAs/SM -> 235 CTAs fit one wave (296 capacity).
#define AS2 264
#define BS2 72
#define SMEM_G ((128 * AS2 + 128 * BS2) * 2)

__device__ __forceinline__ void mma_f16(float* c, uint32_t a0, uint32_t a1,
                                        uint32_t a2, uint32_t a3,
                                        uint32_t b0, uint32_t b1) {
    asm volatile(
        "mma.sync.aligned.m16n8k16.row.col.f32.f16.f16.f32 "
        "{%0,%1,%2,%3}, {%4,%5,%6,%7}, {%8,%9}, {%0,%1,%2,%3};"
        : "+f"(c[0]), "+f"(c[1]), "+f"(c[2]), "+f"(c[3])
        : "r"(a0), "r"(a1), "r"(a2), "r"(a3), "r"(b0), "r"(b1));
}

__global__ void __launch_bounds__(256, 2)
gemm_qkv_kernel(const float* __restrict__ xin,
                const float* __restrict__ bq, const float* __restrict__ bk,
                const float* __restrict__ bv, int l) {
    extern __shared__ __half smemh[];
    __half* sA = smemh;                    // [128][AS2]
    __half* sB = smemh + 128 * AS2;        // [128][BS2]

    const float* __restrict__ Asrc = (l == 0) ? xin : (const float*)g_x;

    int tid = threadIdx.x;
    int wid = tid >> 5, lane = tid & 31;
    int g = lane >> 2, tig = lane & 3;
    int wm = (wid & 3) * 32;
    int wn = (wid >> 2) * 64;
    int m0 = blockIdx.x * 128;

    // ---- load A tile [128 x 256] fp32 -> fp16 into padded SMEM
    for (int i = tid; i < 128 * 64; i += 256) {
        int r = i >> 6;
        int c4 = (i & 63) * 4;
        float4 v = make_float4(0.f, 0.f, 0.f, 0.f);
        if (m0 + r < N_NODES) v = *(const float4*)(Asrc + (size_t)(m0 + r) * DMODEL + c4);
        __half2 h0 = make_half2(__float2half_rn(v.x), __float2half_rn(v.y));
        __half2 h1 = make_half2(__float2half_rn(v.z), __float2half_rn(v.w));
        uint2 u = make_uint2(*(uint32_t*)&h0, *(uint32_t*)&h1);
        *(uint2*)(sA + r * AS2 + c4) = u;
    }

    for (int w = 0; w < 3; w++) {
        const __half* __restrict__ wt = g_wth + (size_t)(l * 3 + w) * DMODEL * DMODEL;
        float* __restrict__ dstp = (w == 0) ? g_q : ((w == 1) ? g_k : g_v);
        const float* __restrict__ bias = (w == 0) ? bq : ((w == 1) ? bk : bv);

        for (int nb = 0; nb < 2; nb++) {
            int n0 = nb * 128;
            float acc[2][8][4];
#pragma unroll
            for (int mi = 0; mi < 2; mi++)
#pragma unroll
                for (int ni = 0; ni < 8; ni++)
#pragma unroll
                    for (int j = 0; j < 4; j++) acc[mi][ni][j] = 0.f;

            for (int kc = 0; kc < 4; kc++) {
                __syncthreads();   // protect sB from previous chunk's readers
                // load B chunk: rows n0..n0+127, k kc*64..+63 (half, 8B per thread-iter)
                for (int i = tid; i < 128 * 16; i += 256) {
                    int nr = i >> 4;
                    int j4 = (i & 15) * 4;
                    uint2 u = *(const uint2*)(wt + (size_t)(n0 + nr) * DMODEL + kc * 64 + j4);
                    *(uint2*)(sB + nr * BS2 + j4) = u;
                }
                __syncthreads();

#pragma unroll
                for (int ks = 0; ks < 4; ks++) {       // 4 x k16 steps cover k=64
                    int kl = ks * 16;                   // local k in chunk (sB)
                    int kg = kc * 64 + kl;              // global k (sA)
                    uint32_t a[2][4];
#pragma unroll
                    for (int mi = 0; mi < 2; mi++) {
                        int r0 = wm + mi * 16 + g;
                        const __half* pa0 = sA + r0 * AS2 + kg + 2 * tig;
                        const __half* pa1 = sA + (r0 + 8) * AS2 + kg + 2 * tig;
                        a[mi][0] = *(const uint32_t*)(pa0);
                        a[mi][1] = *(const uint32_t*)(pa1);
                        a[mi][2] = *(const uint32_t*)(pa0 + 8);
                        a[mi][3] = *(const uint32_t*)(pa1 + 8);
                    }
                    uint32_t b[8][2];
#pragma unroll
                    for (int ni = 0; ni < 8; ni++) {
                        int nr = wn + ni * 8 + g;
                        const __half* pb = sB + nr * BS2 + kl + 2 * tig;
                        b[ni][0] = *(const uint32_t*)(pb);
                        b[ni][1] = *(const uint32_t*)(pb + 8);
                    }
#pragma unroll
                    for (int mi = 0; mi < 2; mi++)
#pragma unroll
                        for (int ni = 0; ni < 8; ni++)
                            mma_f16(acc[mi][ni], a[mi][0], a[mi][1], a[mi][2], a[mi][3],
                                    b[ni][0], b[ni][1]);
                }
            }

            // ---- epilogue: bias + store (c-frag layout identical to tf32 version)
#pragma unroll
            for (int mi = 0; mi < 2; mi++) {
                int r0 = m0 + wm + mi * 16 + g;
                int r1 = r0 + 8;
#pragma unroll
                for (int ni = 0; ni < 8; ni++) {
                    int col = n0 + wn + ni * 8 + tig * 2;
                    float b0 = bias[col], b1 = bias[col + 1];
                    if (r0 < N_NODES) {
                        float2 o0 = make_float2(acc[mi][ni][0] + b0, acc[mi][ni][1] + b1);
                        *(float2*)(dstp + (size_t)r0 * DMODEL + col) = o0;
                    }
                    if (r1 < N_NODES) {
                        float2 o1 = make_float2(acc[mi][ni][2] + b0, acc[mi][ni][3] + b1);
                        *(float2*)(dstp + (size_t)r1 * DMODEL + col) = o1;
                    }
                }
            }
        }
    }
}

// ---------------- attention: warp/node, 8-lane group/head, 2-edge pipelined ----------------
__global__ void attn_kernel(const float* __restrict__ Eemb_l) {
    __shared__ float s_ete[NUM_ET * DMODEL];
    for (int i = threadIdx.x; i < NUM_ET * DMODEL; i += blockDim.x)
        s_ete[i] = Eemb_l[i];
    __syncthreads();

    int gw = (blockIdx.x * blockDim.x + threadIdx.x) >> 5;
    int lane = threadIdx.x & 31;
    if (gw >= N_NODES) return;
    int node = gw;
    int g = lane >> 3, li = lane & 7;
    int dbase = g * 64 + li * 8;

    float4 q0 = *(const float4*)(g_q + (size_t)node * DMODEL + dbase);
    float4 q1 = *(const float4*)(g_q + (size_t)node * DMODEL + dbase + 4);

    int beg = g_off[node], end = g_off[node + 1];
    float m = -INFINITY, den = 0.f;
    float4 acc0 = make_float4(0.f, 0.f, 0.f, 0.f);
    float4 acc1 = make_float4(0.f, 0.f, 0.f, 0.f);
    const float scale = 0.125f;  // 1/sqrt(64)

    int t = beg;
    for (; t + 1 < end; t += 2) {
        int pkA = g_epk[t];
        int pkB = g_epk[t + 1];
        int srcA = pkA & 0xFFFF, etA = pkA >> 16;
        int srcB = pkB & 0xFFFF, etB = pkB >> 16;
        const float* kbA = g_k + (size_t)srcA * DMODEL + dbase;
        const float* vbA = g_v + (size_t)srcA * DMODEL + dbase;
        const float* ebA = s_ete + etA * DMODEL + dbase;
        const float* kbB = g_k + (size_t)srcB * DMODEL + dbase;
        const float* vbB = g_v + (size_t)srcB * DMODEL + dbase;
        const float* ebB = s_ete + etB * DMODEL + dbase;

        float4 kA0 = *(const float4*)(kbA);
        float4 kA1 = *(const float4*)(kbA + 4);
        float4 kB0 = *(const float4*)(kbB);
        float4 kB1 = *(const float4*)(kbB + 4);
        float4 vA0 = *(const float4*)(vbA);
        float4 vA1 = *(const float4*)(vbA + 4);
        float4 vB0 = *(const float4*)(vbB);
        float4 vB1 = *(const float4*)(vbB + 4);
        float4 eA0 = *(const float4*)(ebA);
        float4 eA1 = *(const float4*)(ebA + 4);
        float4 eB0 = *(const float4*)(ebB);
        float4 eB1 = *(const float4*)(ebB + 4);

        float sA = q0.x * (kA0.x + eA0.x) + q0.y * (kA0.y + eA0.y)
                 + q0.z * (kA0.z + eA0.z) + q0.w * (kA0.w + eA0.w)
                 + q1.x * (kA1.x + eA1.x) + q1.y * (kA1.y + eA1.y)
                 + q1.z * (kA1.z + eA1.z) + q1.w * (kA1.w + eA1.w);
        float sB = q0.x * (kB0.x + eB0.x) + q0.y * (kB0.y + eB0.y)
                 + q0.z * (kB0.z + eB0.z) + q0.w * (kB0.w + eB0.w)
                 + q1.x * (kB1.x + eB1.x) + q1.y * (kB1.y + eB1.y)
                 + q1.z * (kB1.z + eB1.z) + q1.w * (kB1.w + eB1.w);

        sA += __shfl_xor_sync(0xffffffffu, sA, 1);
        sB += __shfl_xor_sync(0xffffffffu, sB, 1);
        sA += __shfl_xor_sync(0xffffffffu, sA, 2);
        sB += __shfl_xor_sync(0xffffffffu, sB, 2);
        sA += __shfl_xor_sync(0xffffffffu, sA, 4);
        sB += __shfl_xor_sync(0xffffffffu, sB, 4);
        sA *= scale;
        sB *= scale;

        float nm = fmaxf(m, fmaxf(sA, sB));
        float sc = __expf(m - nm);
        float pA = __expf(sA - nm);
        float pB = __expf(sB - nm);
        den = den * sc + pA + pB;
        m = nm;

        acc0.x = acc0.x * sc + pA * (vA0.x + eA0.x) + pB * (vB0.x + eB0.x);
        acc0.y = acc0.y * sc + pA * (vA0.y + eA0.y) + pB * (vB0.y + eB0.y);
        acc0.z = acc0.z * sc + pA * (vA0.z + eA0.z) + pB * (vB0.z + eB0.z);
        acc0.w = acc0.w * sc + pA * (vA0.w + eA0.w) + pB * (vB0.w + eB0.w);
        acc1.x = acc1.x * sc + pA * (vA1.x + eA1.x) + pB * (vB1.x + eB1.x);
        acc1.y = acc1.y * sc + pA * (vA1.y + eA1.y) + pB * (vB1.y + eB1.y);
        acc1.z = acc1.z * sc + pA * (vA1.z + eA1.z) + pB * (vB1.z + eB1.z);
        acc1.w = acc1.w * sc + pA * (vA1.w + eA1.w) + pB * (vB1.w + eB1.w);
    }
    if (t < end) {
        int pk = g_epk[t];
        int src = pk & 0xFFFF, et = pk >> 16;
        const float* kb = g_k + (size_t)src * DMODEL + dbase;
        const float* vb = g_v + (size_t)src * DMODEL + dbase;
        const float* eb = s_ete + et * DMODEL + dbase;
        float4 k0 = *(const float4*)(kb);
        float4 k1 = *(const float4*)(kb + 4);
        float4 v0 = *(const float4*)(vb);
        float4 v1 = *(const float4*)(vb + 4);
        float4 e0 = *(const float4*)(eb);
        float4 e1 = *(const float4*)(eb + 4);
        float s = q0.x * (k0.x + e0.x) + q0.y * (k0.y + e0.y)
                + q0.z * (k0.z + e0.z) + q0.w * (k0.w + e0.w)
                + q1.x * (k1.x + e1.x) + q1.y * (k1.y + e1.y)
                + q1.z * (k1.z + e1.z) + q1.w * (k1.w + e1.w);
        s += __shfl_xor_sync(0xffffffffu, s, 1);
        s += __shfl_xor_sync(0xffffffffu, s, 2);
        s += __shfl_xor_sync(0xffffffffu, s, 4);
        s *= scale;
        float nm = fmaxf(m, s);
        float sc = __expf(m - nm);
        float p = __expf(s - nm);
        den = den * sc + p;
        m = nm;
        acc0.x = acc0.x * sc + p * (v0.x + e0.x);
        acc0.y = acc0.y * sc + p * (v0.y + e0.y);
        acc0.z = acc0.z * sc + p * (v0.z + e0.z);
        acc0.w = acc0.w * sc + p * (v0.w + e0.w);
        acc1.x = acc1.x * sc + p * (v1.x + e1.x);
        acc1.y = acc1.y * sc + p * (v1.y + e1.y);
        acc1.z = acc1.z * sc + p * (v1.z + e1.z);
        acc1.w = acc1.w * sc + p * (v1.w + e1.w);
    }

    float inv = 1.0f / (den + 1e-16f);
    float o[8] = { acc0.x * inv, acc0.y * inv, acc0.z * inv, acc0.w * inv,
                   acc1.x * inv, acc1.y * inv, acc1.z * inv, acc1.w * inv };
#pragma unroll
    for (int j = 0; j < 8; j++) o[j] = (o[j] > 0.f) ? o[j] : expm1f(o[j]);
    *(float4*)(g_x + (size_t)node * DMODEL + dbase)     = make_float4(o[0], o[1], o[2], o[3]);
    *(float4*)(g_x + (size_t)node * DMODEL + dbase + 4) = make_float4(o[4], o[5], o[6], o[7]);
}

// ---------------- global mean pool: run-length accumulate (batch is sorted) ----------------
#define POOL_NPB 64
__global__ void pool_kernel(const int* __restrict__ batch) {
    __shared__ int s_b[POOL_NPB];
    int d = threadIdx.x;               // dim 0..255
    int n0 = blockIdx.x * POOL_NPB;
    int nend = min(n0 + POOL_NPB, N_NODES);
    int cnt = nend - n0;
    if (d < cnt) s_b[d] = batch[n0 + d];
    __syncthreads();

    int curb = s_b[0];
    float run = 0.f;
    for (int i = 0; i < cnt; i++) {
        int b = s_b[i];
        if (b != curb) {
            atomicAdd(&g_pool[curb * DMODEL + d], run);
            run = 0.f;
            curb = b;
        }
        run += g_x[(size_t)(n0 + i) * DMODEL + d];
    }
    atomicAdd(&g_pool[curb * DMODEL + d], run);

    if (d == 0) {
        int cb = s_b[0];
        float c = 0.f;
        for (int i = 0; i < cnt; i++) {
            if (s_b[i] != cb) { atomicAdd(&g_gcnt[cb], c); c = 0.f; cb = s_b[i]; }
            c += 1.0f;
        }
        atomicAdd(&g_gcnt[cb], c);
    }
}

// ---------------- GRU + FC ----------------
__global__ void gru_kernel(const float* __restrict__ W_ih,
                           const float* __restrict__ b_ih,
                           const float* __restrict__ b_hh,
                           const float* __restrict__ W_fc,
                           const float* __restrict__ b_fc,
                           float* __restrict__ out) {
    __shared__ float gv[DMODEL];
    __shared__ float gi[3 * HID];
    __shared__ float hh[HID];
    int g = blockIdx.x, t = threadIdx.x;
    float cnt = fmaxf(g_gcnt[g], 1.0f);
    if (t < DMODEL) gv[t] = g_pool[g * DMODEL + t] / cnt;
    __syncthreads();
    if (t < 3 * HID) {
        float s = b_ih[t];
        const float* w = W_ih + (size_t)t * DMODEL;
        for (int k = 0; k < DMODEL; k++) s += gv[k] * w[k];
        gi[t] = s;
    }
    __syncthreads();
    if (t < HID) {
        float r = 1.0f / (1.0f + __expf(-(gi[t] + b_hh[t])));
        float z = 1.0f / (1.0f + __expf(-(gi[HID + t] + b_hh[HID + t])));
        float n = tanhf(gi[2 * HID + t] + r * b_hh[2 * HID + t]);
        hh[t] = (1.0f - z) * n;
    }
    __syncthreads();
    if (t < NUM_CLASSES) {
        float s = b_fc[t];
        const float* w = W_fc + (size_t)t * HID;
        for (int k = 0; k < HID; k++) s += hh[k] * w[k];
        out[g * NUM_CLASSES + t] = s;
    }
}

// ---------------- launch ----------------
extern "C" void kernel_launch(void* const* d_in, const int* in_sizes, int n_in,
                              void* d_out, int out_size) {
    const float* x     = (const float*)d_in[0];
    const int*   ei    = (const int*)d_in[1];
    const int*   batch = (const int*)d_in[2];
    const int*   etype = (const int*)d_in[3];
    const float* Wq    = (const float*)d_in[4];
    const float* bq    = (const float*)d_in[5];
    const float* Wk    = (const float*)d_in[6];
    const float* bk    = (const float*)d_in[7];
    const float* Wv    = (const float*)d_in[8];
    const float* bv    = (const float*)d_in[9];
    const float* Eemb  = (const float*)d_in[10];
    const float* W_ih  = (const float*)d_in[11];
    const float* b_ih  = (const float*)d_in[12];
    const float* b_hh  = (const float*)d_in[14];
    const float* W_fc  = (const float*)d_in[15];
    const float* b_fc  = (const float*)d_in[16];
    float* out = (float*)d_out;

    cudaFuncSetAttribute(gemm_qkv_kernel, cudaFuncAttributeMaxDynamicSharedMemorySize, SMEM_G);

    init_kernel<<<64, 256>>>();
    hist_kernel<<<(N_EDGES + 255) / 256, 256>>>(ei);
    scan_kernel<<<1, 1024>>>();
    scatter_kernel<<<(N_EDGES + 255) / 256, 256>>>(ei, etype);
    transpose_w<<<(9 * DMODEL * DMODEL + 255) / 256, 256>>>(Wq, Wk, Wv);

    int gblocks = (N_NODES + 127) / 128;          // 235
    int ablocks = (N_NODES * 32 + 255) / 256;     // one warp per node

    for (int l = 0; l < NUM_LAYERS; l++) {
        gemm_qkv_kernel<<<gblocks, 256, SMEM_G>>>(x, bq + l * DMODEL, bk + l * DMODEL,
                                                  bv + l * DMODEL, l);
        attn_kernel<<<ablocks, 256>>>(Eemb + (size_t)l * NUM_ET * DMODEL);
    }

    pool_kernel<<<(N_NODES + POOL_NPB - 1) / POOL_NPB, 256>>>(batch);
    gru_kernel<<<NUM_GRAPHS, 256>>>(W_ih, b_ih, b_hh, W_fc, b_fc, out);
}